// round 1
// baseline (speedup 1.0000x reference)
#include <cuda_runtime.h>
#include <cuda_bf16.h>
#include <math_constants.h>

#define Bn 2
#define Tn 2048
#define DMn 1024
#define Hn 16
#define DKn 64
#define DVn 64
#define BTn (Bn * Tn)

// Scratch (allocation-free rule: __device__ globals)
__device__ float g_Q[Bn * Hn * Tn * DKn];   // [B,H,T,DK]
__device__ float g_K[Bn * Hn * Tn * DKn];
__device__ float g_V[Bn * Hn * Tn * DVn];
__device__ float g_ctx[BTn * (Hn * DVn)];   // [B*T, H*DV] concat layout

// ---------------------------------------------------------------------------
// QKV projection: out[b,h,t,k] = sum_d x[b,t,d] * w[h,d,k]
// grid: (BT/64, H, 3), block: 256 threads, 64x64 tile, K-step 16
// ---------------------------------------------------------------------------
__global__ __launch_bounds__(256) void proj_kernel(
    const float* __restrict__ xq, const float* __restrict__ xk,
    const float* __restrict__ xv, const float* __restrict__ wq,
    const float* __restrict__ wk, const float* __restrict__ wv)
{
    const int which = blockIdx.z;
    const float* x = which == 0 ? xq : (which == 1 ? xk : xv);
    const float* w = which == 0 ? wq : (which == 1 ? wk : wv);
    float* out     = which == 0 ? g_Q : (which == 1 ? g_K : g_V);

    const int h    = blockIdx.y;
    const int row0 = blockIdx.x * 64;

    __shared__ float As[64][17];     // [row][k] padded
    __shared__ float Bs[16 * 64];    // [k][col] flat, float4-readable

    const int tid = threadIdx.x;
    const int tx  = tid & 15;        // 0..15 -> col group
    const int ty  = tid >> 4;        // 0..15 -> row group

    float acc[4][4] = {};
    const float* wh = w + (size_t)h * DMn * DKn;

    for (int k0 = 0; k0 < DMn; k0 += 16) {
        #pragma unroll
        for (int i = 0; i < 4; i++) {
            int idx = tid + i * 256;           // 0..1023 over 64x16
            int r = idx >> 4, c = idx & 15;
            As[r][c] = x[(size_t)(row0 + r) * DMn + k0 + c];
        }
        #pragma unroll
        for (int i = 0; i < 4; i++) {
            int idx = tid + i * 256;           // 0..1023 over 16x64
            int r = idx >> 6, c = idx & 63;
            Bs[r * 64 + c] = wh[(size_t)(k0 + r) * DKn + c];
        }
        __syncthreads();
        #pragma unroll
        for (int kk = 0; kk < 16; kk++) {
            float a[4];
            #pragma unroll
            for (int i = 0; i < 4; i++) a[i] = As[ty * 4 + i][kk];
            float4 bv = *(const float4*)&Bs[kk * 64 + tx * 4];
            float bb[4] = {bv.x, bv.y, bv.z, bv.w};
            #pragma unroll
            for (int i = 0; i < 4; i++)
                #pragma unroll
                for (int j = 0; j < 4; j++)
                    acc[i][j] += a[i] * bb[j];
        }
        __syncthreads();
    }

    #pragma unroll
    for (int i = 0; i < 4; i++) {
        int bt = row0 + ty * 4 + i;
        int b  = bt >> 11;            // /T (T=2048)
        int t  = bt & 2047;
        float* o = out + ((size_t)((b * Hn + h) * Tn + t)) * DKn;
        #pragma unroll
        for (int j = 0; j < 4; j++) o[tx * 4 + j] = acc[i][j];
    }
}

// ---------------------------------------------------------------------------
// Flash attention (fp32, online softmax). One thread = one query row.
// grid: (T/128, H, B), block: 128 threads. K/V tiles of 64 rows in smem.
// Faithful quirk: s = (qk/dk) * mask[key]; if s == 0 -> -inf.
// ---------------------------------------------------------------------------
__global__ __launch_bounds__(128) void flash_kernel(
    const float* __restrict__ mask)
{
    const int b  = blockIdx.z;
    const int h  = blockIdx.y;
    const int q0 = blockIdx.x * 128;
    const int tid = threadIdx.x;
    const int t  = q0 + tid;

    __shared__ float Ks[64 * 64];
    __shared__ float Vs[64 * 64];
    __shared__ float Ms[64];

    const size_t bh = (size_t)(b * Hn + h);
    const float* Qp = g_Q + (bh * Tn + t) * DKn;
    const float* Kbase = g_K + bh * Tn * DKn;
    const float* Vbase = g_V + bh * Tn * DVn;

    float q[64];
    #pragma unroll
    for (int d = 0; d < 64; d += 4) {
        float4 v = *(const float4*)(Qp + d);
        q[d] = v.x; q[d+1] = v.y; q[d+2] = v.z; q[d+3] = v.w;
    }

    float acc[64] = {};
    float m = -CUDART_INF_F, l = 0.0f;
    const float inv_dk = 1.0f / 64.0f;

    for (int kt0 = 0; kt0 < Tn; kt0 += 64) {
        __syncthreads();   // WAR guard vs previous-iteration smem reads
        #pragma unroll
        for (int i = 0; i < 8; i++) {
            int idx = (tid + i * 128) * 4;   // 4096 floats total
            *(float4*)(Ks + idx) = *(const float4*)(Kbase + kt0 * 64 + idx);
            *(float4*)(Vs + idx) = *(const float4*)(Vbase + kt0 * 64 + idx);
        }
        if (tid < 64) Ms[tid] = mask[b * Tn + kt0 + tid];
        __syncthreads();

        for (int kt = 0; kt < 64; kt++) {
            // dot(q, K[kt]) with 4 partial chains
            const float4* kr = (const float4*)(Ks + kt * 64);
            float s0 = 0.f, s1 = 0.f, s2 = 0.f, s3 = 0.f;
            #pragma unroll
            for (int d4 = 0; d4 < 16; d4++) {
                float4 kv = kr[d4];
                s0 += q[d4*4+0] * kv.x;
                s1 += q[d4*4+1] * kv.y;
                s2 += q[d4*4+2] * kv.z;
                s3 += q[d4*4+3] * kv.w;
            }
            float s = ((s0 + s1) + (s2 + s3)) * inv_dk * Ms[kt];
            if (s == 0.0f) s = -CUDART_INF_F;       // faithful mask quirk

            if (s > -CUDART_INF_F) {
                float p;
                if (s > m) {
                    float scale = __expf(m - s);    // m=-inf -> 0, acc/l are 0
                    l *= scale;
                    #pragma unroll
                    for (int dv = 0; dv < 64; dv++) acc[dv] *= scale;
                    m = s;
                    p = 1.0f;
                } else {
                    p = __expf(s - m);
                }
                l += p;
                const float4* vr = (const float4*)(Vs + kt * 64);
                #pragma unroll
                for (int d4 = 0; d4 < 16; d4++) {
                    float4 vv = vr[d4];
                    acc[d4*4+0] += p * vv.x;
                    acc[d4*4+1] += p * vv.y;
                    acc[d4*4+2] += p * vv.z;
                    acc[d4*4+3] += p * vv.w;
                }
            }
        }
    }

    const float invl = 1.0f / l;
    float* o = g_ctx + ((size_t)(b * Tn + t)) * (Hn * DVn) + h * DVn;
    #pragma unroll
    for (int d = 0; d < 64; d += 4) {
        float4 v;
        v.x = acc[d]   * invl; v.y = acc[d+1] * invl;
        v.z = acc[d+2] * invl; v.w = acc[d+3] * invl;
        *(float4*)(o + d) = v;
    }
}

// ---------------------------------------------------------------------------
// Output projection: out = ctx @ w_o + b_o ; [4096,1024] @ [1024,1024]
// grid: (BT/64, DM/64), block 256, 64x64 tile
// ---------------------------------------------------------------------------
__global__ __launch_bounds__(256) void out_proj_kernel(
    const float* __restrict__ wo, const float* __restrict__ bo,
    float* __restrict__ out)
{
    const int row0 = blockIdx.x * 64;
    const int col0 = blockIdx.y * 64;

    __shared__ float As[64][17];
    __shared__ float Bs[16 * 64];

    const int tid = threadIdx.x;
    const int tx  = tid & 15;
    const int ty  = tid >> 4;

    float acc[4][4] = {};

    for (int k0 = 0; k0 < Hn * DVn; k0 += 16) {
        #pragma unroll
        for (int i = 0; i < 4; i++) {
            int idx = tid + i * 256;
            int r = idx >> 4, c = idx & 15;
            As[r][c] = g_ctx[(size_t)(row0 + r) * (Hn * DVn) + k0 + c];
        }
        #pragma unroll
        for (int i = 0; i < 4; i++) {
            int idx = tid + i * 256;
            int r = idx >> 6, c = idx & 63;
            Bs[r * 64 + c] = wo[(size_t)(k0 + r) * DMn + col0 + c];
        }
        __syncthreads();
        #pragma unroll
        for (int kk = 0; kk < 16; kk++) {
            float a[4];
            #pragma unroll
            for (int i = 0; i < 4; i++) a[i] = As[ty * 4 + i][kk];
            float4 bv = *(const float4*)&Bs[kk * 64 + tx * 4];
            float bb[4] = {bv.x, bv.y, bv.z, bv.w};
            #pragma unroll
            for (int i = 0; i < 4; i++)
                #pragma unroll
                for (int j = 0; j < 4; j++)
                    acc[i][j] += a[i] * bb[j];
        }
        __syncthreads();
    }

    #pragma unroll
    for (int i = 0; i < 4; i++) {
        int r = row0 + ty * 4 + i;
        #pragma unroll
        for (int j = 0; j < 4; j++) {
            int c = col0 + tx * 4 + j;
            out[(size_t)r * DMn + c] = acc[i][j] + bo[c];
        }
    }
}

// ---------------------------------------------------------------------------
extern "C" void kernel_launch(void* const* d_in, const int* in_sizes, int n_in,
                              void* d_out, int out_size)
{
    const float* xq   = (const float*)d_in[0];
    const float* xk   = (const float*)d_in[1];
    const float* xv   = (const float*)d_in[2];
    const float* mask = (const float*)d_in[3];
    const float* w_q  = (const float*)d_in[4];
    const float* w_k  = (const float*)d_in[5];
    const float* w_v  = (const float*)d_in[6];
    const float* w_o  = (const float*)d_in[7];
    const float* b_o  = (const float*)d_in[8];
    float* out        = (float*)d_out;

    dim3 projGrid(BTn / 64, Hn, 3);
    proj_kernel<<<projGrid, 256>>>(xq, xk, xv, w_q, w_k, w_v);

    dim3 flashGrid(Tn / 128, Hn, Bn);
    flash_kernel<<<flashGrid, 128>>>(mask);

    dim3 outGrid(BTn / 64, DMn / 64);
    out_proj_kernel<<<outGrid, 256>>>(w_o, b_o, out);
}

// round 5
// speedup vs baseline: 2.2981x; 2.2981x over previous
#include <cuda_runtime.h>
#include <math_constants.h>
#include <cstdint>

#define Bn 2
#define Tn 2048
#define DMn 1024
#define Hn 16
#define DKn 64
#define DVn 64
#define BTn (Bn * Tn)

// Scratch (allocation-free rule: __device__ globals)
__device__ float g_Q[Bn * Hn * Tn * DKn];   // [B,H,T,DK]
__device__ float g_K[Bn * Hn * Tn * DKn];   // [B,H,T,DK]
__device__ float g_V[Bn * Hn * Tn * DVn];   // [B,H,T,DV]
__device__ float g_ctx[BTn * (Hn * DVn)];   // [B*T, H*DV]

// ===========================================================================
// tf32 mma.sync helpers (base PTX, works on compute_103 target)
// ===========================================================================
__device__ __forceinline__ uint32_t f2tf(float x) {
    uint32_t r;
    asm("cvt.rna.tf32.f32 %0, %1;" : "=r"(r) : "f"(x));
    return r;
}
// split x = hi + lo (both tf32-representable)
__device__ __forceinline__ void tf32_split(float x, uint32_t& hi, uint32_t& lo) {
    hi = f2tf(x);
    lo = f2tf(x - __uint_as_float(hi));
}

// D(16x8) += A(16x8,row) * B(8x8,col);  A,B are tf32 bit patterns in .b32
__device__ __forceinline__ void mma8(float* d, const uint32_t* a, const uint32_t* b) {
    asm volatile(
        "mma.sync.aligned.m16n8k8.row.col.f32.tf32.tf32.f32 "
        "{%0,%1,%2,%3}, {%4,%5,%6,%7}, {%8,%9}, {%0,%1,%2,%3};"
        : "+f"(d[0]), "+f"(d[1]), "+f"(d[2]), "+f"(d[3])
        : "r"(a[0]), "r"(a[1]), "r"(a[2]), "r"(a[3]), "r"(b[0]), "r"(b[1]));
}

// ===========================================================================
// 3xTF32 128x64 GEMM body (K=1024, BK=32), 256 threads = 8 warps (4m x 2n)
// acc ~ fp32-accurate: Al*Bh + Ah*Bl + Ah*Bh
// ===========================================================================
#define AST 36   // As padded stride (floats)
#define BST 72   // Bs padded stride (floats)
#define GS_AH 0
#define GS_AL (128 * AST)
#define GS_BH (2 * 128 * AST)
#define GS_BL (2 * 128 * AST + 32 * BST)
#define GS_TOT (2 * 128 * AST + 2 * 32 * BST)   // 13824 floats = 55296 B

__device__ __forceinline__ void gemm_body3(
    const float* __restrict__ Ag, const float* __restrict__ Bg, int ldb,
    float acc[2][4][4], float* gs)
{
    uint32_t* Ah = (uint32_t*)(gs + GS_AH);
    uint32_t* Al = (uint32_t*)(gs + GS_AL);
    uint32_t* Bh = (uint32_t*)(gs + GS_BH);
    uint32_t* Bl = (uint32_t*)(gs + GS_BL);

    const int tid  = threadIdx.x;
    const int lane = tid & 31;
    const int wid  = tid >> 5;
    const int gid  = lane >> 2;
    const int tig  = lane & 3;
    const int wm   = (wid >> 1) * 32;
    const int wn   = (wid & 1) * 32;

    for (int k0 = 0; k0 < DMn; k0 += 32) {
        #pragma unroll
        for (int i = 0; i < 4; i++) {           // A tile 128x32
            int lin = tid + i * 256;
            int r = lin >> 3, c = (lin & 7) * 4;
            float4 v = *(const float4*)(Ag + (size_t)r * DMn + k0 + c);
            uint4 h, l;
            tf32_split(v.x, h.x, l.x); tf32_split(v.y, h.y, l.y);
            tf32_split(v.z, h.z, l.z); tf32_split(v.w, h.w, l.w);
            *(uint4*)(Ah + r * AST + c) = h;
            *(uint4*)(Al + r * AST + c) = l;
        }
        #pragma unroll
        for (int i = 0; i < 2; i++) {           // B tile 32x64
            int lin = tid + i * 256;
            int r = lin >> 4, c = (lin & 15) * 4;
            float4 v = *(const float4*)(Bg + (size_t)(k0 + r) * ldb + c);
            uint4 h, l;
            tf32_split(v.x, h.x, l.x); tf32_split(v.y, h.y, l.y);
            tf32_split(v.z, h.z, l.z); tf32_split(v.w, h.w, l.w);
            *(uint4*)(Bh + r * BST + c) = h;
            *(uint4*)(Bl + r * BST + c) = l;
        }
        __syncthreads();

        #pragma unroll
        for (int kk = 0; kk < 4; kk++) {
            uint32_t ah[2][4], al[2][4];
            #pragma unroll
            for (int m = 0; m < 2; m++) {
                int r0 = (wm + m * 16 + gid) * AST + kk * 8 + tig;
                int r1 = (wm + m * 16 + 8 + gid) * AST + kk * 8 + tig;
                ah[m][0] = Ah[r0]; ah[m][1] = Ah[r1];
                ah[m][2] = Ah[r0 + 4]; ah[m][3] = Ah[r1 + 4];
                al[m][0] = Al[r0]; al[m][1] = Al[r1];
                al[m][2] = Al[r0 + 4]; al[m][3] = Al[r1 + 4];
            }
            #pragma unroll
            for (int n = 0; n < 4; n++) {
                int b0 = (kk * 8 + tig) * BST + wn + n * 8 + gid;
                int b1 = (kk * 8 + 4 + tig) * BST + wn + n * 8 + gid;
                uint32_t bh[2] = {Bh[b0], Bh[b1]};
                uint32_t bl[2] = {Bl[b0], Bl[b1]};
                #pragma unroll
                for (int m = 0; m < 2; m++) {
                    mma8(acc[m][n], al[m], bh);   // small terms first
                    mma8(acc[m][n], ah[m], bl);
                    mma8(acc[m][n], ah[m], bh);
                }
            }
        }
        __syncthreads();
    }
}

// ---------------------------------------------------------------------------
// QKV projection: grid (BT/128, H, 3), block 256
// ---------------------------------------------------------------------------
__global__ __launch_bounds__(256, 2) void proj_kernel(
    const float* __restrict__ xq, const float* __restrict__ xk,
    const float* __restrict__ xv, const float* __restrict__ wq,
    const float* __restrict__ wk, const float* __restrict__ wv)
{
    extern __shared__ __align__(16) float gs[];

    const int which = blockIdx.z;
    const int h     = blockIdx.y;
    const int row0  = blockIdx.x * 128;

    const float* x = which == 0 ? xq : (which == 1 ? xk : xv);
    const float* w = (which == 0 ? wq : (which == 1 ? wk : wv)) + (size_t)h * DMn * DKn;
    float* outp    = which == 0 ? g_Q : (which == 1 ? g_K : g_V);

    float acc[2][4][4] = {};
    gemm_body3(x + (size_t)row0 * DMn, w, DKn, acc, gs);

    const int lane = threadIdx.x & 31;
    const int wid  = threadIdx.x >> 5;
    const int gid  = lane >> 2;
    const int tig  = lane & 3;
    const int wm   = (wid >> 1) * 32;
    const int wn   = (wid & 1) * 32;

    const int b = row0 >> 11;       // 128-row blocks never straddle batch
    #pragma unroll
    for (int m = 0; m < 2; m++) {
        int r = row0 + wm + m * 16 + gid;
        int t = r & 2047;
        size_t base0 = ((size_t)(b * Hn + h) * Tn + t) * DKn;
        size_t base1 = base0 + 8 * DKn;
        #pragma unroll
        for (int n = 0; n < 4; n++) {
            int c = wn + n * 8 + tig * 2;
            *(float2*)(outp + base0 + c) = make_float2(acc[m][n][0], acc[m][n][1]);
            *(float2*)(outp + base1 + c) = make_float2(acc[m][n][2], acc[m][n][3]);
        }
    }
}

// ---------------------------------------------------------------------------
// Output projection: grid (BT/128, DM/64), block 256
// ---------------------------------------------------------------------------
__global__ __launch_bounds__(256, 2) void out_proj_kernel(
    const float* __restrict__ wo, const float* __restrict__ bo,
    float* __restrict__ out)
{
    extern __shared__ __align__(16) float gs[];

    const int row0 = blockIdx.x * 128;
    const int col0 = blockIdx.y * 64;

    float acc[2][4][4] = {};
    gemm_body3(g_ctx + (size_t)row0 * DMn, wo + col0, DMn, acc, gs);

    const int lane = threadIdx.x & 31;
    const int wid  = threadIdx.x >> 5;
    const int gid  = lane >> 2;
    const int tig  = lane & 3;
    const int wm   = (wid >> 1) * 32;
    const int wn   = (wid & 1) * 32;

    #pragma unroll
    for (int m = 0; m < 2; m++) {
        int r = row0 + wm + m * 16 + gid;
        #pragma unroll
        for (int n = 0; n < 4; n++) {
            int c = col0 + wn + n * 8 + tig * 2;
            float2 bb = *(const float2*)(bo + c);
            *(float2*)(out + (size_t)r * DMn + c) =
                make_float2(acc[m][n][0] + bb.x, acc[m][n][1] + bb.y);
            *(float2*)(out + (size_t)(r + 8) * DMn + c) =
                make_float2(acc[m][n][2] + bb.x, acc[m][n][3] + bb.y);
        }
    }
}

// ---------------------------------------------------------------------------
// Flash attention, tf32 mma.sync. QK uses 3xTF32; PV uses 1x (P in [0,1]).
// grid (T/128, H, B), block 256 (8 warps); warp owns 16 query rows.
// ---------------------------------------------------------------------------
#define KST 68
#define VST 72
#define PST 132
#define FS_KH 0
#define FS_KL (128 * KST)                  // 8704
#define FS_V  (2 * 128 * KST)              // 17408
#define FS_P  (FS_V + 128 * VST)           // 26624
#define FS_M  (FS_P + 8 * 16 * PST)        // 43520
#define FS_TOT (FS_M + 128)                // 43648 floats = 174592 B

__global__ __launch_bounds__(256, 1) void flash_kernel(
    const float* __restrict__ mask)
{
    extern __shared__ __align__(16) float fs[];
    uint32_t* Kh = (uint32_t*)(fs + FS_KH);
    uint32_t* Kl = (uint32_t*)(fs + FS_KL);
    uint32_t* Vsu = (uint32_t*)(fs + FS_V);
    float* Ps = fs + FS_P;
    float* Ms = fs + FS_M;

    const int tid  = threadIdx.x;
    const int lane = tid & 31;
    const int wid  = tid >> 5;
    const int gid  = lane >> 2;
    const int tig  = lane & 3;

    const int b  = blockIdx.z;
    const int h  = blockIdx.y;
    const int q0 = blockIdx.x * 128;
    const size_t bh = (size_t)(b * Hn + h);
    const int qr = q0 + wid * 16;

    // Q fragments hi/lo: warp's 16 rows x 64 dk, register resident
    const float* Qg = g_Q + (bh * Tn + qr) * DKn;
    uint32_t qh[8][4], ql[8][4];
    #pragma unroll
    for (int kk = 0; kk < 8; kk++) {
        tf32_split(Qg[gid * DKn + kk * 8 + tig],           qh[kk][0], ql[kk][0]);
        tf32_split(Qg[(gid + 8) * DKn + kk * 8 + tig],     qh[kk][1], ql[kk][1]);
        tf32_split(Qg[gid * DKn + kk * 8 + 4 + tig],       qh[kk][2], ql[kk][2]);
        tf32_split(Qg[(gid + 8) * DKn + kk * 8 + 4 + tig], qh[kk][3], ql[kk][3]);
    }

    float o[8][4];
    #pragma unroll
    for (int n = 0; n < 8; n++)
        #pragma unroll
        for (int c = 0; c < 4; c++) o[n][c] = 0.0f;

    float m0 = -CUDART_INF_F, m1 = -CUDART_INF_F;
    float l0 = 0.0f, l1 = 0.0f;
    const float inv_dk = 1.0f / 64.0f;
    uint32_t* Pu = (uint32_t*)(Ps + wid * 16 * PST);

    for (int kt0 = 0; kt0 < Tn; kt0 += 128) {
        __syncthreads();   // K/V tiles free for reuse
        const float* Kg = g_K + (bh * Tn + kt0) * DKn;
        const float* Vg = g_V + (bh * Tn + kt0) * DVn;
        #pragma unroll
        for (int i = 0; i < 8; i++) {          // 128x64 each, float4 units
            int lin = tid + i * 256;
            int r = lin >> 4, c = (lin & 15) * 4;
            float4 kv = *(const float4*)(Kg + (size_t)r * DKn + c);
            uint4 hh, ll;
            tf32_split(kv.x, hh.x, ll.x); tf32_split(kv.y, hh.y, ll.y);
            tf32_split(kv.z, hh.z, ll.z); tf32_split(kv.w, hh.w, ll.w);
            *(uint4*)(Kh + r * KST + c) = hh;
            *(uint4*)(Kl + r * KST + c) = ll;
            float4 vv = *(const float4*)(Vg + (size_t)r * DVn + c);
            *(uint4*)(Vsu + r * VST + c) =
                make_uint4(f2tf(vv.x), f2tf(vv.y), f2tf(vv.z), f2tf(vv.w));
        }
        if (tid < 128) Ms[tid] = mask[b * Tn + kt0 + tid];
        __syncthreads();

        // ---- S = Q @ K^T : 3xTF32, warp tile 16 x 128 ----
        float sc[16][4];
        #pragma unroll
        for (int n = 0; n < 16; n++)
            #pragma unroll
            for (int c = 0; c < 4; c++) sc[n][c] = 0.0f;
        #pragma unroll
        for (int kk = 0; kk < 8; kk++) {
            #pragma unroll
            for (int n = 0; n < 16; n++) {
                int base = (n * 8 + gid) * KST + kk * 8 + tig;
                uint32_t bh2[2] = {Kh[base], Kh[base + 4]};
                uint32_t bl2[2] = {Kl[base], Kl[base + 4]};
                mma8(sc[n], ql[kk], bh2);
                mma8(sc[n], qh[kk], bl2);
                mma8(sc[n], qh[kk], bh2);
            }
        }

        // ---- masked scale + faithful zero->-inf quirk + row max ----
        float mx0 = -CUDART_INF_F, mx1 = -CUDART_INF_F;
        #pragma unroll
        for (int n = 0; n < 16; n++) {
            float mk0 = Ms[n * 8 + tig * 2];
            float mk1 = Ms[n * 8 + tig * 2 + 1];
            float s0 = sc[n][0] * inv_dk * mk0; s0 = (s0 == 0.0f) ? -CUDART_INF_F : s0;
            float s1 = sc[n][1] * inv_dk * mk1; s1 = (s1 == 0.0f) ? -CUDART_INF_F : s1;
            float s2 = sc[n][2] * inv_dk * mk0; s2 = (s2 == 0.0f) ? -CUDART_INF_F : s2;
            float s3 = sc[n][3] * inv_dk * mk1; s3 = (s3 == 0.0f) ? -CUDART_INF_F : s3;
            sc[n][0] = s0; sc[n][1] = s1; sc[n][2] = s2; sc[n][3] = s3;
            mx0 = fmaxf(mx0, fmaxf(s0, s1));
            mx1 = fmaxf(mx1, fmaxf(s2, s3));
        }
        mx0 = fmaxf(mx0, __shfl_xor_sync(0xffffffffu, mx0, 1));
        mx0 = fmaxf(mx0, __shfl_xor_sync(0xffffffffu, mx0, 2));
        mx1 = fmaxf(mx1, __shfl_xor_sync(0xffffffffu, mx1, 1));
        mx1 = fmaxf(mx1, __shfl_xor_sync(0xffffffffu, mx1, 2));

        float mn0 = fmaxf(m0, mx0);
        float mn1 = fmaxf(m1, mx1);
        float scale0 = (m0 >= mn0) ? 1.0f : __expf(m0 - mn0);
        float scale1 = (m1 >= mn1) ? 1.0f : __expf(m1 - mn1);

        // ---- exp, accumulate l, write P (tf32) to per-warp smem ----
        float ls0 = 0.0f, ls1 = 0.0f;
        #pragma unroll
        for (int n = 0; n < 16; n++) {
            float p0 = __expf(sc[n][0] - mn0);
            float p1 = __expf(sc[n][1] - mn0);
            float p2 = __expf(sc[n][2] - mn1);
            float p3 = __expf(sc[n][3] - mn1);
            ls0 += p0 + p1;
            ls1 += p2 + p3;
            *(uint2*)&Pu[gid * PST + n * 8 + tig * 2]       = make_uint2(f2tf(p0), f2tf(p1));
            *(uint2*)&Pu[(gid + 8) * PST + n * 8 + tig * 2] = make_uint2(f2tf(p2), f2tf(p3));
        }
        l0 = l0 * scale0 + ls0;
        l1 = l1 * scale1 + ls1;
        m0 = mn0; m1 = mn1;

        // ---- rescale O, then O += P @ V (1x tf32) ----
        #pragma unroll
        for (int n = 0; n < 8; n++) {
            o[n][0] *= scale0; o[n][1] *= scale0;
            o[n][2] *= scale1; o[n][3] *= scale1;
        }
        __syncwarp();
        #pragma unroll
        for (int kk = 0; kk < 16; kk++) {
            uint32_t a[4];
            a[0] = Pu[gid * PST + kk * 8 + tig];
            a[1] = Pu[(gid + 8) * PST + kk * 8 + tig];
            a[2] = Pu[gid * PST + kk * 8 + 4 + tig];
            a[3] = Pu[(gid + 8) * PST + kk * 8 + 4 + tig];
            #pragma unroll
            for (int n = 0; n < 8; n++) {
                uint32_t bq[2];
                bq[0] = Vsu[(kk * 8 + tig) * VST + n * 8 + gid];
                bq[1] = Vsu[(kk * 8 + 4 + tig) * VST + n * 8 + gid];
                mma8(o[n], a, bq);
            }
        }
        __syncwarp();   // P reads done before next tile's writes
    }

    // ---- finalize: row sums across the 4-lane groups, normalize, store ----
    l0 += __shfl_xor_sync(0xffffffffu, l0, 1);
    l0 += __shfl_xor_sync(0xffffffffu, l0, 2);
    l1 += __shfl_xor_sync(0xffffffffu, l1, 1);
    l1 += __shfl_xor_sync(0xffffffffu, l1, 2);
    const float i0 = 1.0f / l0;
    const float i1 = 1.0f / l1;

    float* og0 = g_ctx + (size_t)(b * Tn + qr + gid) * (Hn * DVn) + h * DVn;
    float* og1 = og0 + 8 * (Hn * DVn);
    #pragma unroll
    for (int n = 0; n < 8; n++) {
        *(float2*)(og0 + n * 8 + tig * 2) = make_float2(o[n][0] * i0, o[n][1] * i0);
        *(float2*)(og1 + n * 8 + tig * 2) = make_float2(o[n][2] * i1, o[n][3] * i1);
    }
}

// ---------------------------------------------------------------------------
extern "C" void kernel_launch(void* const* d_in, const int* in_sizes, int n_in,
                              void* d_out, int out_size)
{
    const float* xq   = (const float*)d_in[0];
    const float* xk   = (const float*)d_in[1];
    const float* xv   = (const float*)d_in[2];
    const float* mask = (const float*)d_in[3];
    const float* w_q  = (const float*)d_in[4];
    const float* w_k  = (const float*)d_in[5];
    const float* w_v  = (const float*)d_in[6];
    const float* w_o  = (const float*)d_in[7];
    const float* b_o  = (const float*)d_in[8];
    float* out        = (float*)d_out;

    const int gemm_smem  = GS_TOT * (int)sizeof(float);   // 55296 B
    const int flash_smem = FS_TOT * (int)sizeof(float);   // 174592 B
    cudaFuncSetAttribute(proj_kernel,
                         cudaFuncAttributeMaxDynamicSharedMemorySize, gemm_smem);
    cudaFuncSetAttribute(out_proj_kernel,
                         cudaFuncAttributeMaxDynamicSharedMemorySize, gemm_smem);
    cudaFuncSetAttribute(flash_kernel,
                         cudaFuncAttributeMaxDynamicSharedMemorySize, flash_smem);

    dim3 projGrid(BTn / 128, Hn, 3);
    proj_kernel<<<projGrid, 256, gemm_smem>>>(xq, xk, xv, w_q, w_k, w_v);

    dim3 flashGrid(Tn / 128, Hn, Bn);
    flash_kernel<<<flashGrid, 256, flash_smem>>>(mask);

    dim3 outGrid(BTn / 128, DMn / 64);
    out_proj_kernel<<<outGrid, 256, gemm_smem>>>(w_o, b_o, out);
}

// round 6
// speedup vs baseline: 3.4615x; 1.5062x over previous
#include <cuda_runtime.h>
#include <cuda_bf16.h>
#include <math_constants.h>
#include <cstdint>

#define Bn 2
#define Tn 2048
#define DMn 1024
#define Hn 16
#define DKn 64
#define DVn 64
#define BTn (Bn * Tn)

// Scratch (allocation-free rule: __device__ globals)
__device__ float g_Q[Bn * Hn * Tn * DKn];   // [B,H,T,DK]
__device__ float g_K[Bn * Hn * Tn * DKn];   // [B,H,T,DK]
__device__ float g_V[Bn * Hn * Tn * DVn];   // [B,H,T,DV]
__device__ float g_ctx[BTn * (Hn * DVn)];   // [B*T, H*DV]

// ===========================================================================
// mma.sync helpers (base PTX, compute_103-safe)
// ===========================================================================
__device__ __forceinline__ uint32_t f2tf(float x) {
    uint32_t r;
    asm("cvt.rna.tf32.f32 %0, %1;" : "=r"(r) : "f"(x));
    return r;
}
// pack two floats -> bf16x2 (.x = e in low half, .y = o in high half)
__device__ __forceinline__ uint32_t pack_bf16(float e, float o) {
    __nv_bfloat162 t = __floats2bfloat162_rn(e, o);
    return *(uint32_t*)&t;
}
// bf16 split of a pair: (e,o) -> hi pair + lo pair (x ~ hi + lo)
__device__ __forceinline__ void bf16_split2(float e, float o,
                                            uint32_t& hi, uint32_t& lo) {
    float eh = __bfloat162float(__float2bfloat16_rn(e));
    float oh = __bfloat162float(__float2bfloat16_rn(o));
    hi = pack_bf16(eh, oh);
    lo = pack_bf16(e - eh, o - oh);
}

// D(16x8) += A(16x8 row, tf32) * B(8x8 col, tf32)
__device__ __forceinline__ void mma8(float* d, const uint32_t* a, const uint32_t* b) {
    asm volatile(
        "mma.sync.aligned.m16n8k8.row.col.f32.tf32.tf32.f32 "
        "{%0,%1,%2,%3}, {%4,%5,%6,%7}, {%8,%9}, {%0,%1,%2,%3};"
        : "+f"(d[0]), "+f"(d[1]), "+f"(d[2]), "+f"(d[3])
        : "r"(a[0]), "r"(a[1]), "r"(a[2]), "r"(a[3]), "r"(b[0]), "r"(b[1]));
}
// D(16x8) += A(16x16 row, bf16x2) * B(16x8 col, bf16x2)
__device__ __forceinline__ void mma16(float* d, const uint32_t* a, const uint32_t* b) {
    asm volatile(
        "mma.sync.aligned.m16n8k16.row.col.f32.bf16.bf16.f32 "
        "{%0,%1,%2,%3}, {%4,%5,%6,%7}, {%8,%9}, {%0,%1,%2,%3};"
        : "+f"(d[0]), "+f"(d[1]), "+f"(d[2]), "+f"(d[3])
        : "r"(a[0]), "r"(a[1]), "r"(a[2]), "r"(a[3]), "r"(b[0]), "r"(b[1]));
}

// ===========================================================================
// 3xBF16 128x64 GEMM body (K=1024, BK=32), 256 threads = 8 warps (4m x 2n)
// acc ~ fp32-accurate: Al*Bh + Ah*Bl + Ah*Bh   (bf16 split, k16 MMAs)
// Packed tiles: u32 element = (k_even, k_odd) bf16 pair.
// ===========================================================================
#define ASTu 20   // A stride in u32 (16 k-pairs + pad)
#define BSTu 72   // B stride in u32 (64 cols + pad 8 -> conflict-free tig*72%32=8*tig)
#define GS_AH 0
#define GS_AL (128 * ASTu)
#define GS_BH (2 * 128 * ASTu)
#define GS_BL (2 * 128 * ASTu + 16 * BSTu)
#define GS_TOT (2 * 128 * ASTu + 2 * 16 * BSTu)   // 7424 u32 = 29696 B

__device__ __forceinline__ void gemm_body3(
    const float* __restrict__ Ag, const float* __restrict__ Bg, int ldb,
    float acc[2][4][4], uint32_t* gs)
{
    uint32_t* Ah = gs + GS_AH;
    uint32_t* Al = gs + GS_AL;
    uint32_t* Bh = gs + GS_BH;
    uint32_t* Bl = gs + GS_BL;

    const int tid  = threadIdx.x;
    const int lane = tid & 31;
    const int wid  = tid >> 5;
    const int gid  = lane >> 2;
    const int tig  = lane & 3;
    const int wm   = (wid >> 1) * 32;
    const int wn   = (wid & 1) * 32;

    for (int k0 = 0; k0 < DMn; k0 += 32) {
        // A tile 128x32: 4 float4 loads/thread; pack k-pairs along the row
        #pragma unroll
        for (int i = 0; i < 4; i++) {
            int lin = tid + i * 256;
            int r = lin >> 3, c = (lin & 7) * 4;
            float4 v = *(const float4*)(Ag + (size_t)r * DMn + k0 + c);
            uint32_t h0, l0, h1, l1;
            bf16_split2(v.x, v.y, h0, l0);
            bf16_split2(v.z, v.w, h1, l1);
            *(uint2*)(Ah + r * ASTu + (c >> 1)) = make_uint2(h0, h1);
            *(uint2*)(Al + r * ASTu + (c >> 1)) = make_uint2(l0, l1);
        }
        // B tile 32x64: thread loads rows 2kp,2kp+1 at col c..c+3, packs k-pairs
        {
            int kp = tid >> 4;
            int c  = (tid & 15) * 4;
            float4 v0 = *(const float4*)(Bg + (size_t)(k0 + 2 * kp) * ldb + c);
            float4 v1 = *(const float4*)(Bg + (size_t)(k0 + 2 * kp + 1) * ldb + c);
            uint4 h, l;
            bf16_split2(v0.x, v1.x, h.x, l.x);
            bf16_split2(v0.y, v1.y, h.y, l.y);
            bf16_split2(v0.z, v1.z, h.z, l.z);
            bf16_split2(v0.w, v1.w, h.w, l.w);
            *(uint4*)(Bh + kp * BSTu + c) = h;
            *(uint4*)(Bl + kp * BSTu + c) = l;
        }
        __syncthreads();

        #pragma unroll
        for (int kk = 0; kk < 2; kk++) {          // two k16 steps cover BK=32
            uint32_t ah[2][4], al[2][4];
            #pragma unroll
            for (int m = 0; m < 2; m++) {
                int r0 = (wm + m * 16 + gid) * ASTu + kk * 8 + tig;
                int r1 = (wm + m * 16 + 8 + gid) * ASTu + kk * 8 + tig;
                ah[m][0] = Ah[r0]; ah[m][1] = Ah[r1];
                ah[m][2] = Ah[r0 + 4]; ah[m][3] = Ah[r1 + 4];
                al[m][0] = Al[r0]; al[m][1] = Al[r1];
                al[m][2] = Al[r0 + 4]; al[m][3] = Al[r1 + 4];
            }
            #pragma unroll
            for (int n = 0; n < 4; n++) {
                int b0 = (kk * 8 + tig) * BSTu + wn + n * 8 + gid;
                int b1 = (kk * 8 + 4 + tig) * BSTu + wn + n * 8 + gid;
                uint32_t bh[2] = {Bh[b0], Bh[b1]};
                uint32_t bl[2] = {Bl[b0], Bl[b1]};
                #pragma unroll
                for (int m = 0; m < 2; m++) {
                    mma16(acc[m][n], al[m], bh);
                    mma16(acc[m][n], ah[m], bl);
                    mma16(acc[m][n], ah[m], bh);
                }
            }
        }
        __syncthreads();
    }
}

// ---------------------------------------------------------------------------
// QKV projection: grid (BT/128, H, 3), block 256
// ---------------------------------------------------------------------------
__global__ __launch_bounds__(256, 2) void proj_kernel(
    const float* __restrict__ xq, const float* __restrict__ xk,
    const float* __restrict__ xv, const float* __restrict__ wq,
    const float* __restrict__ wk, const float* __restrict__ wv)
{
    extern __shared__ __align__(16) uint32_t gs[];

    const int which = blockIdx.z;
    const int h     = blockIdx.y;
    const int row0  = blockIdx.x * 128;

    const float* x = which == 0 ? xq : (which == 1 ? xk : xv);
    const float* w = (which == 0 ? wq : (which == 1 ? wk : wv)) + (size_t)h * DMn * DKn;
    float* outp    = which == 0 ? g_Q : (which == 1 ? g_K : g_V);

    float acc[2][4][4] = {};
    gemm_body3(x + (size_t)row0 * DMn, w, DKn, acc, gs);

    const int lane = threadIdx.x & 31;
    const int wid  = threadIdx.x >> 5;
    const int gid  = lane >> 2;
    const int tig  = lane & 3;
    const int wm   = (wid >> 1) * 32;
    const int wn   = (wid & 1) * 32;

    const int b = row0 >> 11;       // 128-row blocks never straddle batch
    #pragma unroll
    for (int m = 0; m < 2; m++) {
        int r = row0 + wm + m * 16 + gid;
        int t = r & 2047;
        size_t base0 = ((size_t)(b * Hn + h) * Tn + t) * DKn;
        size_t base1 = base0 + 8 * DKn;
        #pragma unroll
        for (int n = 0; n < 4; n++) {
            int c = wn + n * 8 + tig * 2;
            *(float2*)(outp + base0 + c) = make_float2(acc[m][n][0], acc[m][n][1]);
            *(float2*)(outp + base1 + c) = make_float2(acc[m][n][2], acc[m][n][3]);
        }
    }
}

// ---------------------------------------------------------------------------
// Output projection: grid (BT/128, DM/64), block 256
// ---------------------------------------------------------------------------
__global__ __launch_bounds__(256, 2) void out_proj_kernel(
    const float* __restrict__ wo, const float* __restrict__ bo,
    float* __restrict__ out)
{
    extern __shared__ __align__(16) uint32_t gs[];

    const int row0 = blockIdx.x * 128;
    const int col0 = blockIdx.y * 64;

    float acc[2][4][4] = {};
    gemm_body3(g_ctx + (size_t)row0 * DMn, wo + col0, DMn, acc, gs);

    const int lane = threadIdx.x & 31;
    const int wid  = threadIdx.x >> 5;
    const int gid  = lane >> 2;
    const int tig  = lane & 3;
    const int wm   = (wid >> 1) * 32;
    const int wn   = (wid & 1) * 32;

    #pragma unroll
    for (int m = 0; m < 2; m++) {
        int r = row0 + wm + m * 16 + gid;
        #pragma unroll
        for (int n = 0; n < 4; n++) {
            int c = col0 + wn + n * 8 + tig * 2;
            float2 bb = *(const float2*)(bo + c);
            *(float2*)(out + (size_t)r * DMn + c) =
                make_float2(acc[m][n][0] + bb.x, acc[m][n][1] + bb.y);
            *(float2*)(out + (size_t)(r + 8) * DMn + c) =
                make_float2(acc[m][n][2] + bb.x, acc[m][n][3] + bb.y);
        }
    }
}

// ---------------------------------------------------------------------------
// Flash attention: QK = 3xBF16 (k16), PV = 1xTF32 (k8, P in [0,1]).
// grid (T/128, H, B), block 256 (8 warps); warp owns 16 query rows.
// ---------------------------------------------------------------------------
#define KSTu 36                           // K tile stride in u32 (32 dk-pairs + pad)
#define VST  72
#define PST  132
#define FS_KH 0
#define FS_KL (128 * KSTu)                // 4608
#define FS_V  (2 * 128 * KSTu)            // 9216
#define FS_P  (FS_V + 128 * VST)          // 18432
#define FS_M  (FS_P + 8 * 16 * PST)       // 35328
#define FS_TOT (FS_M + 128)               // 35456 u32 = 141824 B

__global__ __launch_bounds__(256, 1) void flash_kernel(
    const float* __restrict__ mask)
{
    extern __shared__ __align__(16) uint32_t fsu[];
    uint32_t* Kh  = fsu + FS_KH;
    uint32_t* Kl  = fsu + FS_KL;
    uint32_t* Vsu = fsu + FS_V;
    float*    Ps  = (float*)(fsu + FS_P);
    float*    Ms  = (float*)(fsu + FS_M);

    const int tid  = threadIdx.x;
    const int lane = tid & 31;
    const int wid  = tid >> 5;
    const int gid  = lane >> 2;
    const int tig  = lane & 3;

    const int b  = blockIdx.z;
    const int h  = blockIdx.y;
    const int q0 = blockIdx.x * 128;
    const size_t bh = (size_t)(b * Hn + h);
    const int qr = q0 + wid * 16;

    // Q fragments hi/lo (bf16 pairs): 4 k16 steps over DK=64, register resident
    const float* Qg = g_Q + (bh * Tn + qr) * DKn;
    uint32_t qh[4][4], ql[4][4];
    #pragma unroll
    for (int kk = 0; kk < 4; kk++) {
        float2 e;
        e = *(const float2*)(Qg + gid * DKn + kk * 16 + 2 * tig);
        bf16_split2(e.x, e.y, qh[kk][0], ql[kk][0]);
        e = *(const float2*)(Qg + (gid + 8) * DKn + kk * 16 + 2 * tig);
        bf16_split2(e.x, e.y, qh[kk][1], ql[kk][1]);
        e = *(const float2*)(Qg + gid * DKn + kk * 16 + 2 * tig + 8);
        bf16_split2(e.x, e.y, qh[kk][2], ql[kk][2]);
        e = *(const float2*)(Qg + (gid + 8) * DKn + kk * 16 + 2 * tig + 8);
        bf16_split2(e.x, e.y, qh[kk][3], ql[kk][3]);
    }

    float o[8][4];
    #pragma unroll
    for (int n = 0; n < 8; n++)
        #pragma unroll
        for (int c = 0; c < 4; c++) o[n][c] = 0.0f;

    float m0 = -CUDART_INF_F, m1 = -CUDART_INF_F;
    float l0 = 0.0f, l1 = 0.0f;
    const float inv_dk = 1.0f / 64.0f;
    uint32_t* Pu = (uint32_t*)(Ps + wid * 16 * PST);

    for (int kt0 = 0; kt0 < Tn; kt0 += 128) {
        __syncthreads();   // K/V tiles free for reuse
        const float* Kg = g_K + (bh * Tn + kt0) * DKn;
        const float* Vg = g_V + (bh * Tn + kt0) * DVn;
        #pragma unroll
        for (int i = 0; i < 8; i++) {          // 128x64 each, float4 units
            int lin = tid + i * 256;
            int r = lin >> 4, c = (lin & 15) * 4;
            float4 kv = *(const float4*)(Kg + (size_t)r * DKn + c);
            uint32_t h0, l0b, h1, l1b;
            bf16_split2(kv.x, kv.y, h0, l0b);
            bf16_split2(kv.z, kv.w, h1, l1b);
            *(uint2*)(Kh + r * KSTu + (c >> 1)) = make_uint2(h0, h1);
            *(uint2*)(Kl + r * KSTu + (c >> 1)) = make_uint2(l0b, l1b);
            float4 vv = *(const float4*)(Vg + (size_t)r * DVn + c);
            *(uint4*)(Vsu + r * VST + c) =
                make_uint4(f2tf(vv.x), f2tf(vv.y), f2tf(vv.z), f2tf(vv.w));
        }
        if (tid < 128) Ms[tid] = mask[b * Tn + kt0 + tid];
        __syncthreads();

        // ---- S = Q @ K^T : 3xBF16, warp tile 16 x 128 ----
        float sc[16][4];
        #pragma unroll
        for (int n = 0; n < 16; n++)
            #pragma unroll
            for (int c = 0; c < 4; c++) sc[n][c] = 0.0f;
        #pragma unroll
        for (int kk = 0; kk < 4; kk++) {
            #pragma unroll
            for (int n = 0; n < 16; n++) {
                int base = (n * 8 + gid) * KSTu + kk * 8 + tig;
                uint32_t bh2[2] = {Kh[base], Kh[base + 4]};
                uint32_t bl2[2] = {Kl[base], Kl[base + 4]};
                mma16(sc[n], ql[kk], bh2);
                mma16(sc[n], qh[kk], bl2);
                mma16(sc[n], qh[kk], bh2);
            }
        }

        // ---- masked scale + faithful zero->-inf quirk + row max ----
        float mx0 = -CUDART_INF_F, mx1 = -CUDART_INF_F;
        #pragma unroll
        for (int n = 0; n < 16; n++) {
            float mk0 = Ms[n * 8 + tig * 2];
            float mk1 = Ms[n * 8 + tig * 2 + 1];
            float s0 = sc[n][0] * inv_dk * mk0; s0 = (s0 == 0.0f) ? -CUDART_INF_F : s0;
            float s1 = sc[n][1] * inv_dk * mk1; s1 = (s1 == 0.0f) ? -CUDART_INF_F : s1;
            float s2 = sc[n][2] * inv_dk * mk0; s2 = (s2 == 0.0f) ? -CUDART_INF_F : s2;
            float s3 = sc[n][3] * inv_dk * mk1; s3 = (s3 == 0.0f) ? -CUDART_INF_F : s3;
            sc[n][0] = s0; sc[n][1] = s1; sc[n][2] = s2; sc[n][3] = s3;
            mx0 = fmaxf(mx0, fmaxf(s0, s1));
            mx1 = fmaxf(mx1, fmaxf(s2, s3));
        }
        mx0 = fmaxf(mx0, __shfl_xor_sync(0xffffffffu, mx0, 1));
        mx0 = fmaxf(mx0, __shfl_xor_sync(0xffffffffu, mx0, 2));
        mx1 = fmaxf(mx1, __shfl_xor_sync(0xffffffffu, mx1, 1));
        mx1 = fmaxf(mx1, __shfl_xor_sync(0xffffffffu, mx1, 2));

        float mn0 = fmaxf(m0, mx0);
        float mn1 = fmaxf(m1, mx1);
        float scale0 = (m0 >= mn0) ? 1.0f : __expf(m0 - mn0);
        float scale1 = (m1 >= mn1) ? 1.0f : __expf(m1 - mn1);

        // ---- exp, accumulate l, write P (tf32) to per-warp smem ----
        float ls0 = 0.0f, ls1 = 0.0f;
        #pragma unroll
        for (int n = 0; n < 16; n++) {
            float p0 = __expf(sc[n][0] - mn0);
            float p1 = __expf(sc[n][1] - mn0);
            float p2 = __expf(sc[n][2] - mn1);
            float p3 = __expf(sc[n][3] - mn1);
            ls0 += p0 + p1;
            ls1 += p2 + p3;
            *(uint2*)&Pu[gid * PST + n * 8 + tig * 2]       = make_uint2(f2tf(p0), f2tf(p1));
            *(uint2*)&Pu[(gid + 8) * PST + n * 8 + tig * 2] = make_uint2(f2tf(p2), f2tf(p3));
        }
        l0 = l0 * scale0 + ls0;
        l1 = l1 * scale1 + ls1;
        m0 = mn0; m1 = mn1;

        // ---- rescale O, then O += P @ V (1x tf32, k8) ----
        #pragma unroll
        for (int n = 0; n < 8; n++) {
            o[n][0] *= scale0; o[n][1] *= scale0;
            o[n][2] *= scale1; o[n][3] *= scale1;
        }
        __syncwarp();
        #pragma unroll
        for (int kk = 0; kk < 16; kk++) {
            uint32_t a[4];
            a[0] = Pu[gid * PST + kk * 8 + tig];
            a[1] = Pu[(gid + 8) * PST + kk * 8 + tig];
            a[2] = Pu[gid * PST + kk * 8 + 4 + tig];
            a[3] = Pu[(gid + 8) * PST + kk * 8 + 4 + tig];
            #pragma unroll
            for (int n = 0; n < 8; n++) {
                uint32_t bq[2];
                bq[0] = Vsu[(kk * 8 + tig) * VST + n * 8 + gid];
                bq[1] = Vsu[(kk * 8 + 4 + tig) * VST + n * 8 + gid];
                mma8(o[n], a, bq);
            }
        }
        __syncwarp();   // P reads done before next tile's writes
    }

    // ---- finalize: row sums across the 4-lane groups, normalize, store ----
    l0 += __shfl_xor_sync(0xffffffffu, l0, 1);
    l0 += __shfl_xor_sync(0xffffffffu, l0, 2);
    l1 += __shfl_xor_sync(0xffffffffu, l1, 1);
    l1 += __shfl_xor_sync(0xffffffffu, l1, 2);
    const float i0 = 1.0f / l0;
    const float i1 = 1.0f / l1;

    float* og0 = g_ctx + (size_t)(b * Tn + qr + gid) * (Hn * DVn) + h * DVn;
    float* og1 = og0 + 8 * (Hn * DVn);
    #pragma unroll
    for (int n = 0; n < 8; n++) {
        *(float2*)(og0 + n * 8 + tig * 2) = make_float2(o[n][0] * i0, o[n][1] * i0);
        *(float2*)(og1 + n * 8 + tig * 2) = make_float2(o[n][2] * i1, o[n][3] * i1);
    }
}

// ---------------------------------------------------------------------------
extern "C" void kernel_launch(void* const* d_in, const int* in_sizes, int n_in,
                              void* d_out, int out_size)
{
    const float* xq   = (const float*)d_in[0];
    const float* xk   = (const float*)d_in[1];
    const float* xv   = (const float*)d_in[2];
    const float* mask = (const float*)d_in[3];
    const float* w_q  = (const float*)d_in[4];
    const float* w_k  = (const float*)d_in[5];
    const float* w_v  = (const float*)d_in[6];
    const float* w_o  = (const float*)d_in[7];
    const float* b_o  = (const float*)d_in[8];
    float* out        = (float*)d_out;

    const int gemm_smem  = GS_TOT * (int)sizeof(uint32_t);   // 29696 B
    const int flash_smem = FS_TOT * (int)sizeof(uint32_t);   // 141824 B
    cudaFuncSetAttribute(proj_kernel,
                         cudaFuncAttributeMaxDynamicSharedMemorySize, gemm_smem);
    cudaFuncSetAttribute(out_proj_kernel,
                         cudaFuncAttributeMaxDynamicSharedMemorySize, gemm_smem);
    cudaFuncSetAttribute(flash_kernel,
                         cudaFuncAttributeMaxDynamicSharedMemorySize, flash_smem);

    dim3 projGrid(BTn / 128, Hn, 3);
    proj_kernel<<<projGrid, 256, gemm_smem>>>(xq, xk, xv, w_q, w_k, w_v);

    dim3 flashGrid(Tn / 128, Hn, Bn);
    flash_kernel<<<flashGrid, 256, flash_smem>>>(mask);

    dim3 outGrid(BTn / 128, DMn / 64);
    out_proj_kernel<<<outGrid, 256, gemm_smem>>>(w_o, b_o, out);
}